// round 6
// baseline (speedup 1.0000x reference)
#include <cuda_runtime.h>
#include <math_constants.h>

// Sparsemax (faithful unsorted math) over the last axis.
// x: (8192, 2048) fp32 rows. R6: one CTA/row, 128 threads, 16 elts/thread.
// 4 front-batched LDG.128/thread (MLP_p1=4), ~12 CTAs/SM of independent
// barrier domains to overlap load/compute phases across CTAs.

#define ROW_K   2048
#define TPB     128
#define EPT     16         // ROW_K / TPB
#define NV4     (EPT / 4)  // float4 loads per thread
#define NWARP   (TPB / 32)

// Order-preserving float -> uint key (exact, handles -inf/negatives).
__device__ __forceinline__ unsigned f32_order_key(float v) {
    unsigned b = __float_as_uint(v);
    return b ^ (((int)b >> 31) | 0x80000000u);
}
__device__ __forceinline__ float f32_from_key(unsigned k) {
    unsigned b = k ^ ((~(int)k >> 31) | 0x80000000u);
    return __uint_as_float(b);
}

__global__ void __launch_bounds__(TPB)
sparsemax_row_kernel(const float* __restrict__ x, float* __restrict__ out)
{
    __shared__ float s_wsum[NWARP];   // per-warp data totals
    __shared__ float s_rk[NWARP];     // per-warp kmax
    __shared__ float s_rt[NWARP];     // per-warp tmax

    const int tid  = threadIdx.x;
    const int lane = tid & 31;
    const int warp = tid >> 5;

    const size_t row_off = (size_t)blockIdx.x * ROW_K;
    const float4* __restrict__ xin  = (const float4*)(x   + row_off);
    float4*       __restrict__ xout = (float4*)      (out + row_off);

    // ---- load 16 contiguous floats (4 float4s, front-batched) ----
    float4 v[NV4];
    #pragma unroll
    for (int i = 0; i < NV4; ++i) v[i] = xin[tid * NV4 + i];

    float z[EPT];
    #pragma unroll
    for (int i = 0; i < NV4; ++i) {
        z[i*4+0] = v[i].x; z[i*4+1] = v[i].y;
        z[i*4+2] = v[i].z; z[i*4+3] = v[i].w;
    }

    // ---- thread-local sequential sum (matches reference eval order) ----
    float tot = 0.0f;
    #pragma unroll
    for (int e = 0; e < EPT; ++e) tot = __fadd_rn(tot, z[e]);

    // ---- warp inclusive scan of thread totals (5 shfl) ----
    float inc = tot;
    #pragma unroll
    for (int d = 1; d < 32; d <<= 1) {
        float u = __shfl_up_sync(0xffffffffu, inc, d);
        if (lane >= d) inc += u;
    }
    if (lane == 31) s_wsum[warp] = inc;   // warp total
    __syncthreads();                      // barrier #1

    // exclusive carry: prior threads in warp + totals of prior warps
    float carry = inc - tot;
    #pragma unroll
    for (int w = 0; w < NWARP; ++w)
        if (w < warp) carry += s_wsum[w];

    // ---- mask + partial reductions, sequential running sum from carry ----
    // left = 1 + (k+1)*z[k] (unfused mul+add, matching the ref's rounding)
    // right = cumsum(z)[k] ; mask = left <= right ; kmax/tmax over !mask
    unsigned kmaxi = 0u;
    float tmax = -CUDART_INF_F;
    float run  = carry;
    const int base = tid * EPT;
    #pragma unroll
    for (int e = 0; e < EPT; ++e) {
        run = __fadd_rn(run, z[e]);
        const unsigned kk = (unsigned)(base + e + 1);
        float left = __fadd_rn(1.0f, __fmul_rn((float)kk, z[e]));
        if (!(left <= run)) {
            kmaxi = max(kmaxi, kk);
            tmax  = fmaxf(tmax, run);
        }
    }

    // ---- warp reduce via single-instruction REDUX (integer, order-keyed) ----
    kmaxi = __reduce_max_sync(0xffffffffu, kmaxi);
    unsigned tkey = __reduce_max_sync(0xffffffffu, f32_order_key(tmax));
    if (lane == 0) { s_rk[warp] = (float)kmaxi; s_rt[warp] = f32_from_key(tkey); }
    __syncthreads();                      // barrier #2

    // ---- every thread folds the 4 warp results and computes tau ----
    float km = s_rk[0], tm = s_rt[0];
    #pragma unroll
    for (int w = 1; w < NWARP; ++w) {
        km = fmaxf(km, s_rk[w]);
        tm = fmaxf(tm, s_rt[w]);
    }
    const float tau = __fdiv_rn(__fadd_rn(tm, -1.0f), km);

    // ---- out = relu(x - tau), 4 float4 stores ----
    #pragma unroll
    for (int e = 0; e < EPT; ++e) z[e] = fmaxf(z[e] - tau, 0.0f);
    #pragma unroll
    for (int i = 0; i < NV4; ++i) {
        float4 o = { z[i*4+0], z[i*4+1], z[i*4+2], z[i*4+3] };
        xout[tid * NV4 + i] = o;
    }
}

extern "C" void kernel_launch(void* const* d_in, const int* in_sizes, int n_in,
                              void* d_out, int out_size)
{
    const float* x = (const float*)d_in[0];
    float* out = (float*)d_out;
    int rows = (in_sizes && in_sizes[0] > 0) ? (in_sizes[0] / ROW_K) : (out_size / ROW_K);
    sparsemax_row_kernel<<<rows, TPB>>>(x, out);
}

// round 7
// speedup vs baseline: 1.0829x; 1.0829x over previous
#include <cuda_runtime.h>
#include <math_constants.h>

// Sparsemax (faithful unsorted math) over the last axis. x: (8192, 2048) fp32.
// R7: one CTA/row, 256 threads. Thread t owns float4 #t and #(256+t)
// => all LDG.128/STG.128 perfectly coalesced (halves L1 wavefronts vs R5).
// Dual lo/hi scan supplies the cumsum carries; float-domain k tracking;
// redux-based folds. 2 barriers, regs ~30 (no spill).

#define ROW_K   2048
#define TPB     256
#define NWARP   (TPB / 32)
#define HI_OFF  (ROW_K / 8)   // 256 float4s = element offset 1024

// Order-preserving float -> uint key (exact, handles -inf/negatives).
__device__ __forceinline__ unsigned f32_order_key(float v) {
    unsigned b = __float_as_uint(v);
    return b ^ (((int)b >> 31) | 0x80000000u);
}
__device__ __forceinline__ float f32_from_key(unsigned k) {
    unsigned b = k ^ ((~(int)k >> 31) | 0x80000000u);
    return __uint_as_float(b);
}

__global__ void __launch_bounds__(TPB, 8)
sparsemax_row_kernel(const float* __restrict__ x, float* __restrict__ out)
{
    __shared__ float    s_lo[NWARP];   // per-warp lo-chunk totals
    __shared__ float    s_hi[NWARP];   // per-warp hi-chunk totals
    __shared__ unsigned s_k[NWARP];    // per-warp kmax (float bits, >=0)
    __shared__ unsigned s_t[NWARP];    // per-warp tmax order-key

    const int tid  = threadIdx.x;
    const int lane = tid & 31;
    const int warp = tid >> 5;

    const size_t row_off = (size_t)blockIdx.x * ROW_K;
    const float4* __restrict__ xin  = (const float4*)(x   + row_off);
    float4*       __restrict__ xout = (float4*)      (out + row_off);

    // ---- coalesced loads: float4 #tid (elems 4t..4t+3) and #(256+tid) ----
    float4 a = xin[tid];           // lo chunk
    float4 b = xin[HI_OFF + tid];  // hi chunk (elems 1024+4t ..)

    // ---- per-chunk sequential totals (element order preserved) ----
    float tlo = __fadd_rn(__fadd_rn(__fadd_rn(a.x, a.y), a.z), a.w);
    float thi = __fadd_rn(__fadd_rn(__fadd_rn(b.x, b.y), b.z), b.w);

    // ---- warp inclusive scans of lo and hi thread totals ----
    float ilo = tlo, ihi = thi;
    #pragma unroll
    for (int d = 1; d < 32; d <<= 1) {
        float ulo = __shfl_up_sync(0xffffffffu, ilo, d);
        float uhi = __shfl_up_sync(0xffffffffu, ihi, d);
        if (lane >= d) { ilo += ulo; ihi += uhi; }
    }
    if (lane == 31) { s_lo[warp] = ilo; s_hi[warp] = ihi; }
    __syncthreads();                               // barrier #1

    // ---- inter-warp mini-scan: lanes 0-7 scan lo warp totals,
    //      lanes 8-15 scan hi warp totals (segmented width-8 shfl) ----
    float v = 0.0f;
    if (lane < 8)        v = s_lo[lane];
    else if (lane < 16)  v = s_hi[lane - 8];
    #pragma unroll
    for (int d = 1; d < 8; d <<= 1) {
        float u = __shfl_up_sync(0xffffffffu, v, d, 8);
        if ((lane & 7) >= d) v += u;
    }
    const float TLo = __shfl_sync(0xffffffffu, v, 7);               // total of all lo
    const int   wsrc = (warp > 0) ? (warp - 1) : 0;
    float PLo = __shfl_sync(0xffffffffu, v, wsrc);                  // excl lo prefix
    float PHi = __shfl_sync(0xffffffffu, v, 8 + wsrc);              // excl hi prefix
    if (warp == 0) { PLo = 0.0f; PHi = 0.0f; }

    const float carry_lo = PLo + (ilo - tlo);
    const float carry_hi = TLo + PHi + (ihi - thi);

    // ---- mask + partial reductions (float-domain k) ----
    // left = 1 + k*z (unfused mul+add, matching ref rounding); right = cumsum
    float kmaxf = 0.0f;
    float tmax  = -CUDART_INF_F;
    {
        float run = carry_lo;
        const float kb = (float)(4 * tid);         // exact (<2^24)
        const float zc[4] = { a.x, a.y, a.z, a.w };
        #pragma unroll
        for (int e = 0; e < 4; ++e) {
            run = __fadd_rn(run, zc[e]);
            const float kf = kb + (float)(e + 1);
            const float left = __fadd_rn(1.0f, __fmul_rn(kf, zc[e]));
            if (!(left <= run)) { kmaxf = fmaxf(kmaxf, kf); tmax = fmaxf(tmax, run); }
        }
    }
    {
        float run = carry_hi;
        const float kb = (float)(ROW_K / 2 + 4 * tid);
        const float zc[4] = { b.x, b.y, b.z, b.w };
        #pragma unroll
        for (int e = 0; e < 4; ++e) {
            run = __fadd_rn(run, zc[e]);
            const float kf = kb + (float)(e + 1);
            const float left = __fadd_rn(1.0f, __fmul_rn(kf, zc[e]));
            if (!(left <= run)) { kmaxf = fmaxf(kmaxf, kf); tmax = fmaxf(tmax, run); }
        }
    }

    // ---- warp reduce: kmaxf >= 0 so raw bits are order-monotone ----
    unsigned kbits = __reduce_max_sync(0xffffffffu, __float_as_uint(kmaxf));
    unsigned tkey  = __reduce_max_sync(0xffffffffu, f32_order_key(tmax));
    if (lane == 0) { s_k[warp] = kbits; s_t[warp] = tkey; }
    __syncthreads();                               // barrier #2

    // ---- block fold via redux over lanes 0-7 ----
    unsigned kin = (lane < NWARP) ? s_k[lane] : 0u;
    unsigned tin = (lane < NWARP) ? s_t[lane] : 0u;
    const float km = __uint_as_float(__reduce_max_sync(0xffffffffu, kin));
    const float tm = f32_from_key(__reduce_max_sync(0xffffffffu, tin));
    const float tau = __fdiv_rn(__fadd_rn(tm, -1.0f), km);

    // ---- out = relu(x - tau), coalesced stores ----
    float4 oa = { fmaxf(a.x - tau, 0.0f), fmaxf(a.y - tau, 0.0f),
                  fmaxf(a.z - tau, 0.0f), fmaxf(a.w - tau, 0.0f) };
    float4 ob = { fmaxf(b.x - tau, 0.0f), fmaxf(b.y - tau, 0.0f),
                  fmaxf(b.z - tau, 0.0f), fmaxf(b.w - tau, 0.0f) };
    xout[tid]          = oa;
    xout[HI_OFF + tid] = ob;
}

extern "C" void kernel_launch(void* const* d_in, const int* in_sizes, int n_in,
                              void* d_out, int out_size)
{
    const float* x = (const float*)d_in[0];
    float* out = (float*)d_out;
    int rows = (in_sizes && in_sizes[0] > 0) ? (in_sizes[0] / ROW_K) : (out_size / ROW_K);
    sparsemax_row_kernel<<<rows, TPB>>>(x, out);
}